// round 1
// baseline (speedup 1.0000x reference)
#include <cuda_runtime.h>
#include <mma.h>

using namespace nvcuda;

// Scratch intermediates (allocation-free rule: __device__ globals).
// h1p: [B=1024][j1=64][1024]  permuted layout: pos = r*64 + p2  (l1 = p2*16 + r)
// h2r: [B=1024][j3=64][k3=1024]
__device__ float g_h1p[67108864];
__device__ float g_h2r[67108864];

struct MainBuf {
    float A[2][128 * 20];   // [row][k] padded ldm=20
    float B[2][16 * 132];   // [k][col] padded ldm=132
};
union SmemU {
    MainBuf m;
    float stage[128 * 68];  // epilogue staging, ldm=68
};

// ---------------------------------------------------------------------------
// GEMM1: per j1, C[1024x1024] = gatherX[1024x200] @ k1[j1][200x1024] + b1[j1]
// writes h1p with (r,p2) permutation folded into the store.
// ---------------------------------------------------------------------------
__global__ __launch_bounds__(256) void gemm1_kernel(
    const float* __restrict__ x, const float* __restrict__ k1,
    const float* __restrict__ b1)
{
    const int n0  = blockIdx.x * 128;
    const int m0  = blockIdx.y * 128;
    const int j1  = blockIdx.z;
    const int tid = threadIdx.x;
    const int bx = j1 >> 3, by = j1 & 7;

    __shared__ SmemU sh;

    const int w  = tid >> 5;
    const int wr = w >> 1;   // 0..3  (row group of 32)
    const int wc = w & 1;    // 0..1  (col group of 64)

    wmma::fragment<wmma::accumulator, 16, 16, 8, float> acc[2][4];
#pragma unroll
    for (int i = 0; i < 2; i++)
#pragma unroll
        for (int j = 0; j < 4; j++) wmma::fill_fragment(acc[i][j], 0.0f);

    const int arow = tid >> 1;          // 0..127
    const int akb  = (tid & 1) * 8;     // 0 or 8
    const int bkk  = tid >> 4;          // 0..15
    const int bnn  = (tid & 15) * 8;    // 0..120
    const int bidx = m0 + arow;         // batch row
    const int xrowbase = bidx * 12800;

    float aR[8], bR[8];

    // ---- prefetch chunk 0 ----
#pragma unroll
    for (int i = 0; i < 8; i++) {
        int k = akb + i;
        float v = 0.0f;
        if (k < 200) {
            int wq = k >> 1;
            int wx = wq / 10;
            int wy = wq - wx * 10;
            int c  = k & 1;
            v = x[xrowbase + ((bx * 10 + wx) * 80 + by * 10 + wy) * 2 + c];
        }
        aR[i] = wmma::__float_to_tf32(v);
    }
    {
        int kb = bkk;
        if (kb < 200) {
            const float4* p = reinterpret_cast<const float4*>(
                k1 + ((j1 * 200 + kb) << 10) + n0 + bnn);
            float4 v0 = p[0], v1 = p[1];
            bR[0] = v0.x; bR[1] = v0.y; bR[2] = v0.z; bR[3] = v0.w;
            bR[4] = v1.x; bR[5] = v1.y; bR[6] = v1.z; bR[7] = v1.w;
        } else {
#pragma unroll
            for (int i = 0; i < 8; i++) bR[i] = 0.0f;
        }
#pragma unroll
        for (int i = 0; i < 8; i++) bR[i] = wmma::__float_to_tf32(bR[i]);
    }
    {
        float* As = sh.m.A[0];
        float* Bs = sh.m.B[0];
#pragma unroll
        for (int i = 0; i < 8; i++) As[arow * 20 + akb + i] = aR[i];
#pragma unroll
        for (int i = 0; i < 8; i++) Bs[bkk * 132 + bnn + i] = bR[i];
    }
    __syncthreads();

    int cur = 0;
    const int NC = 13;  // ceil(200/16)
    for (int cidx = 0; cidx < NC; ++cidx) {
        const bool more = (cidx + 1 < NC);
        if (more) {
            const int kt = (cidx + 1) * 16;
#pragma unroll
            for (int i = 0; i < 8; i++) {
                int k = kt + akb + i;
                float v = 0.0f;
                if (k < 200) {
                    int wq = k >> 1;
                    int wx = wq / 10;
                    int wy = wq - wx * 10;
                    int c  = k & 1;
                    v = x[xrowbase + ((bx * 10 + wx) * 80 + by * 10 + wy) * 2 + c];
                }
                aR[i] = wmma::__float_to_tf32(v);
            }
            int kb = kt + bkk;
            if (kb < 200) {
                const float4* p = reinterpret_cast<const float4*>(
                    k1 + ((j1 * 200 + kb) << 10) + n0 + bnn);
                float4 v0 = p[0], v1 = p[1];
                bR[0] = v0.x; bR[1] = v0.y; bR[2] = v0.z; bR[3] = v0.w;
                bR[4] = v1.x; bR[5] = v1.y; bR[6] = v1.z; bR[7] = v1.w;
            } else {
#pragma unroll
                for (int i = 0; i < 8; i++) bR[i] = 0.0f;
            }
#pragma unroll
            for (int i = 0; i < 8; i++) bR[i] = wmma::__float_to_tf32(bR[i]);
        }

        const float* As = sh.m.A[cur];
        const float* Bs = sh.m.B[cur];
#pragma unroll
        for (int ks = 0; ks < 16; ks += 8) {
            wmma::fragment<wmma::matrix_a, 16, 16, 8, wmma::precision::tf32, wmma::row_major> af[2];
            wmma::fragment<wmma::matrix_b, 16, 16, 8, wmma::precision::tf32, wmma::row_major> bf[4];
#pragma unroll
            for (int i = 0; i < 2; i++)
                wmma::load_matrix_sync(af[i], As + (wr * 32 + i * 16) * 20 + ks, 20);
#pragma unroll
            for (int j = 0; j < 4; j++)
                wmma::load_matrix_sync(bf[j], Bs + ks * 132 + wc * 64 + j * 16, 132);
#pragma unroll
            for (int i = 0; i < 2; i++)
#pragma unroll
                for (int j = 0; j < 4; j++)
                    wmma::mma_sync(acc[i][j], af[i], bf[j], acc[i][j]);
        }

        if (more) {
            float* As2 = sh.m.A[cur ^ 1];
            float* Bs2 = sh.m.B[cur ^ 1];
#pragma unroll
            for (int i = 0; i < 8; i++) As2[arow * 20 + akb + i] = aR[i];
#pragma unroll
            for (int i = 0; i < 8; i++) Bs2[bkk * 132 + bnn + i] = bR[i];
        }
        __syncthreads();
        cur ^= 1;
    }

    // Epilogue: bias + permuted store via shared staging, two column halves.
#pragma unroll
    for (int h = 0; h < 2; ++h) {
        if (wc == h) {
#pragma unroll
            for (int i = 0; i < 2; i++)
#pragma unroll
                for (int j = 0; j < 4; j++)
                    wmma::store_matrix_sync(
                        sh.stage + (wr * 32 + i * 16) * 68 + j * 16,
                        acc[i][j], 68, wmma::mem_row_major);
        }
        __syncthreads();
        for (int e = tid; e < 128 * 64; e += 256) {
            int row = e >> 6, cc = e & 63;
            int l1 = n0 + h * 64 + cc;
            float v = sh.stage[row * 68 + cc] + b1[(j1 << 10) + l1];
            int r = l1 & 15, p2 = l1 >> 4;
            g_h1p[(((m0 + row) * 64 + j1) << 10) + r * 64 + p2] = v;
        }
        __syncthreads();
    }
}

// ---------------------------------------------------------------------------
// GEMM2: per j2, out[b,j2,0:16] = h1p-slice[b,0:16] @ k2[j2][16x16] + b2[j2]
// fully coalesced (16 contiguous floats in, 16 contiguous out). fp32 exact.
// ---------------------------------------------------------------------------
__global__ __launch_bounds__(128) void gemm2_kernel(
    const float* __restrict__ k2, const float* __restrict__ b2)
{
    const int j2  = blockIdx.x;
    const int bg  = blockIdx.y;
    const int tid = threadIdx.x;

    __shared__ float wgt[256];
    __shared__ float bias[16];

    reinterpret_cast<float2*>(wgt)[tid] =
        reinterpret_cast<const float2*>(k2 + j2 * 256)[tid];
    if (tid < 16) bias[tid] = b2[j2 * 16 + tid];
    __syncthreads();

    const int r    = j2 >> 8;
    const int j1   = (j2 >> 2) & 63;
    const int p2hi = j2 & 3;
    const int b    = bg * 128 + tid;

    const float4* src = reinterpret_cast<const float4*>(
        g_h1p + (((b * 64 + j1) << 10) + (r << 6) + (p2hi << 4)));
    float in[16];
#pragma unroll
    for (int q = 0; q < 4; q++) {
        float4 v = src[q];
        in[q * 4 + 0] = v.x; in[q * 4 + 1] = v.y;
        in[q * 4 + 2] = v.z; in[q * 4 + 3] = v.w;
    }

    float out[16];
#pragma unroll
    for (int l = 0; l < 16; l++) out[l] = bias[l];
#pragma unroll
    for (int k = 0; k < 16; k++) {
        float a = in[k];
#pragma unroll
        for (int l = 0; l < 16; l++) out[l] += a * wgt[k * 16 + l];
    }

    const int j3 = r * 4 + (j1 >> 4);
    float4* dst = reinterpret_cast<float4*>(
        g_h2r + (((b * 64 + j3) << 10) + ((j1 & 15) << 6) + (p2hi << 4)));
#pragma unroll
    for (int q = 0; q < 4; q++)
        dst[q] = make_float4(out[q * 4 + 0], out[q * 4 + 1],
                             out[q * 4 + 2], out[q * 4 + 3]);
}

// ---------------------------------------------------------------------------
// GEMM3: per j3, C[1024x200] = h2r[1024x1024] @ k3[j3][1024x200] + b3[j3]
// output scattered to final [B,80,80,2] layout.
// ---------------------------------------------------------------------------
__global__ __launch_bounds__(256) void gemm3_kernel(
    const float* __restrict__ k3w, const float* __restrict__ b3,
    float* __restrict__ out)
{
    const int n0  = blockIdx.x * 128;   // 0 or 128
    const int m0  = blockIdx.y * 128;
    const int j3  = blockIdx.z;
    const int tid = threadIdx.x;

    __shared__ SmemU sh;

    const int w  = tid >> 5;
    const int wr = w >> 1;
    const int wc = w & 1;

    wmma::fragment<wmma::accumulator, 16, 16, 8, float> acc[2][4];
#pragma unroll
    for (int i = 0; i < 2; i++)
#pragma unroll
        for (int j = 0; j < 4; j++) wmma::fill_fragment(acc[i][j], 0.0f);

    const int arow = tid >> 1;
    const int akb  = (tid & 1) * 8;
    const int bkk  = tid >> 4;
    const int bnn  = (tid & 15) * 8;
    const int bidx = m0 + arow;
    const int abase = ((bidx * 64 + j3) << 10);
    const int wbase = j3 * 204800;

    float aR[8], bR[8];

    // prefetch chunk 0
    {
        const float4* p = reinterpret_cast<const float4*>(g_h2r + abase + akb);
        float4 v0 = p[0], v1 = p[1];
        aR[0] = v0.x; aR[1] = v0.y; aR[2] = v0.z; aR[3] = v0.w;
        aR[4] = v1.x; aR[5] = v1.y; aR[6] = v1.z; aR[7] = v1.w;
#pragma unroll
        for (int i = 0; i < 8; i++) aR[i] = wmma::__float_to_tf32(aR[i]);

        const float* bp = k3w + wbase + bkk * 200 + n0 + bnn;
        if (n0 + bnn + 8 <= 200) {
            const float4* q = reinterpret_cast<const float4*>(bp);
            float4 u0 = q[0], u1 = q[1];
            bR[0] = u0.x; bR[1] = u0.y; bR[2] = u0.z; bR[3] = u0.w;
            bR[4] = u1.x; bR[5] = u1.y; bR[6] = u1.z; bR[7] = u1.w;
        } else {
#pragma unroll
            for (int i = 0; i < 8; i++)
                bR[i] = (n0 + bnn + i < 200) ? bp[i] : 0.0f;
        }
#pragma unroll
        for (int i = 0; i < 8; i++) bR[i] = wmma::__float_to_tf32(bR[i]);

        float* As = sh.m.A[0];
        float* Bs = sh.m.B[0];
#pragma unroll
        for (int i = 0; i < 8; i++) As[arow * 20 + akb + i] = aR[i];
#pragma unroll
        for (int i = 0; i < 8; i++) Bs[bkk * 132 + bnn + i] = bR[i];
    }
    __syncthreads();

    int cur = 0;
    const int NC = 64;  // K = 1024
    for (int cidx = 0; cidx < NC; ++cidx) {
        const bool more = (cidx + 1 < NC);
        if (more) {
            const int kt = (cidx + 1) * 16;
            const float4* p = reinterpret_cast<const float4*>(g_h2r + abase + kt + akb);
            float4 v0 = p[0], v1 = p[1];
            aR[0] = v0.x; aR[1] = v0.y; aR[2] = v0.z; aR[3] = v0.w;
            aR[4] = v1.x; aR[5] = v1.y; aR[6] = v1.z; aR[7] = v1.w;
#pragma unroll
            for (int i = 0; i < 8; i++) aR[i] = wmma::__float_to_tf32(aR[i]);

            const float* bp = k3w + wbase + (kt + bkk) * 200 + n0 + bnn;
            if (n0 + bnn + 8 <= 200) {
                const float4* q = reinterpret_cast<const float4*>(bp);
                float4 u0 = q[0], u1 = q[1];
                bR[0] = u0.x; bR[1] = u0.y; bR[2] = u0.z; bR[3] = u0.w;
                bR[4] = u1.x; bR[5] = u1.y; bR[6] = u1.z; bR[7] = u1.w;
            } else {
#pragma unroll
                for (int i = 0; i < 8; i++)
                    bR[i] = (n0 + bnn + i < 200) ? bp[i] : 0.0f;
            }
#pragma unroll
            for (int i = 0; i < 8; i++) bR[i] = wmma::__float_to_tf32(bR[i]);
        }

        const float* As = sh.m.A[cur];
        const float* Bs = sh.m.B[cur];
#pragma unroll
        for (int ks = 0; ks < 16; ks += 8) {
            wmma::fragment<wmma::matrix_a, 16, 16, 8, wmma::precision::tf32, wmma::row_major> af[2];
            wmma::fragment<wmma::matrix_b, 16, 16, 8, wmma::precision::tf32, wmma::row_major> bf[4];
#pragma unroll
            for (int i = 0; i < 2; i++)
                wmma::load_matrix_sync(af[i], As + (wr * 32 + i * 16) * 20 + ks, 20);
#pragma unroll
            for (int j = 0; j < 4; j++)
                wmma::load_matrix_sync(bf[j], Bs + ks * 132 + wc * 64 + j * 16, 132);
#pragma unroll
            for (int i = 0; i < 2; i++)
#pragma unroll
                for (int j = 0; j < 4; j++)
                    wmma::mma_sync(acc[i][j], af[i], bf[j], acc[i][j]);
        }

        if (more) {
            float* As2 = sh.m.A[cur ^ 1];
            float* Bs2 = sh.m.B[cur ^ 1];
#pragma unroll
            for (int i = 0; i < 8; i++) As2[arow * 20 + akb + i] = aR[i];
#pragma unroll
            for (int i = 0; i < 8; i++) Bs2[bkk * 132 + bnn + i] = bR[i];
        }
        __syncthreads();
        cur ^= 1;
    }

    // Epilogue: bias + scatter to [B,80,80,2]
#pragma unroll
    for (int h = 0; h < 2; ++h) {
        if (wc == h) {
#pragma unroll
            for (int i = 0; i < 2; i++)
#pragma unroll
                for (int j = 0; j < 4; j++)
                    wmma::store_matrix_sync(
                        sh.stage + (wr * 32 + i * 16) * 68 + j * 16,
                        acc[i][j], 68, wmma::mem_row_major);
        }
        __syncthreads();
        for (int e = tid; e < 128 * 64; e += 256) {
            int row = e >> 6, cc = e & 63;
            int l3 = n0 + h * 64 + cc;
            if (l3 < 200) {
                float v = sh.stage[row * 68 + cc] + b3[j3 * 200 + l3];
                int wq  = l3 >> 1, c = l3 & 1;
                int w2x = wq / 10;
                int w2y = wq - w2x * 10;
                int b2x = j3 >> 3, b2y = j3 & 7;
                out[(m0 + row) * 12800 +
                    ((b2x * 10 + w2x) * 80 + b2y * 10 + w2y) * 2 + c] = v;
            }
        }
        __syncthreads();
    }
}

extern "C" void kernel_launch(void* const* d_in, const int* in_sizes, int n_in,
                              void* d_out, int out_size) {
    const float* x   = (const float*)d_in[0];
    const float* k1  = (const float*)d_in[1];
    const float* b1  = (const float*)d_in[2];
    const float* k2  = (const float*)d_in[3];
    const float* b2  = (const float*)d_in[4];
    const float* k3w = (const float*)d_in[5];
    const float* b3  = (const float*)d_in[6];
    float* out = (float*)d_out;

    gemm1_kernel<<<dim3(8, 8, 64), 256>>>(x, k1, b1);
    gemm2_kernel<<<dim3(4096, 8), 128>>>(k2, b2);
    gemm3_kernel<<<dim3(2, 8, 64), 256>>>(k3w, b3, out);
}

// round 2
// speedup vs baseline: 1.0000x; 1.0000x over previous
#include <cuda_runtime.h>
#include <mma.h>

using namespace nvcuda;

// Scratch intermediates (allocation-free rule: __device__ globals).
// h1p: [B=1024][j1=64][1024]  permuted layout: pos = r*64 + p2  (l1 = p2*16 + r)
// h2r: [B=1024][j3=64][k3=1024]
__device__ float g_h1p[67108864];
__device__ float g_h2r[67108864];

struct MainBuf {
    float A[2][128 * 20];   // [row][k] padded ldm=20
    float B[2][16 * 132];   // [k][col] padded ldm=132
};
union SmemU {
    MainBuf m;
    float stage[128 * 68];  // epilogue staging, ldm=68
};

// ---------------------------------------------------------------------------
// GEMM1: per j1, C[1024x1024] = gatherX[1024x200] @ k1[j1][200x1024] + b1[j1]
// writes h1p with (r,p2) permutation folded into the store.
// ---------------------------------------------------------------------------
__global__ __launch_bounds__(256) void gemm1_kernel(
    const float* __restrict__ x, const float* __restrict__ k1,
    const float* __restrict__ b1)
{
    const int n0  = blockIdx.x * 128;
    const int m0  = blockIdx.y * 128;
    const int j1  = blockIdx.z;
    const int tid = threadIdx.x;
    const int bx = j1 >> 3, by = j1 & 7;

    __shared__ SmemU sh;

    const int w  = tid >> 5;
    const int wr = w >> 1;   // 0..3  (row group of 32)
    const int wc = w & 1;    // 0..1  (col group of 64)

    wmma::fragment<wmma::accumulator, 16, 16, 8, float> acc[2][4];
#pragma unroll
    for (int i = 0; i < 2; i++)
#pragma unroll
        for (int j = 0; j < 4; j++) wmma::fill_fragment(acc[i][j], 0.0f);

    const int arow = tid >> 1;          // 0..127
    const int akb  = (tid & 1) * 8;     // 0 or 8
    const int bkk  = tid >> 4;          // 0..15
    const int bnn  = (tid & 15) * 8;    // 0..120
    const int bidx = m0 + arow;         // batch row
    const int xrowbase = bidx * 12800;

    float aR[8], bR[8];

    // ---- prefetch chunk 0 ----
#pragma unroll
    for (int i = 0; i < 8; i++) {
        int k = akb + i;
        float v = 0.0f;
        if (k < 200) {
            int wq = k >> 1;
            int wx = wq / 10;
            int wy = wq - wx * 10;
            int c  = k & 1;
            v = x[xrowbase + ((bx * 10 + wx) * 80 + by * 10 + wy) * 2 + c];
        }
        aR[i] = wmma::__float_to_tf32(v);
    }
    {
        int kb = bkk;
        if (kb < 200) {
            const float4* p = reinterpret_cast<const float4*>(
                k1 + ((j1 * 200 + kb) << 10) + n0 + bnn);
            float4 v0 = p[0], v1 = p[1];
            bR[0] = v0.x; bR[1] = v0.y; bR[2] = v0.z; bR[3] = v0.w;
            bR[4] = v1.x; bR[5] = v1.y; bR[6] = v1.z; bR[7] = v1.w;
        } else {
#pragma unroll
            for (int i = 0; i < 8; i++) bR[i] = 0.0f;
        }
#pragma unroll
        for (int i = 0; i < 8; i++) bR[i] = wmma::__float_to_tf32(bR[i]);
    }
    {
        float* As = sh.m.A[0];
        float* Bs = sh.m.B[0];
#pragma unroll
        for (int i = 0; i < 8; i++) As[arow * 20 + akb + i] = aR[i];
#pragma unroll
        for (int i = 0; i < 8; i++) Bs[bkk * 132 + bnn + i] = bR[i];
    }
    __syncthreads();

    int cur = 0;
    const int NC = 13;  // ceil(200/16)
    for (int cidx = 0; cidx < NC; ++cidx) {
        const bool more = (cidx + 1 < NC);
        if (more) {
            const int kt = (cidx + 1) * 16;
#pragma unroll
            for (int i = 0; i < 8; i++) {
                int k = kt + akb + i;
                float v = 0.0f;
                if (k < 200) {
                    int wq = k >> 1;
                    int wx = wq / 10;
                    int wy = wq - wx * 10;
                    int c  = k & 1;
                    v = x[xrowbase + ((bx * 10 + wx) * 80 + by * 10 + wy) * 2 + c];
                }
                aR[i] = wmma::__float_to_tf32(v);
            }
            int kb = kt + bkk;
            if (kb < 200) {
                const float4* p = reinterpret_cast<const float4*>(
                    k1 + ((j1 * 200 + kb) << 10) + n0 + bnn);
                float4 v0 = p[0], v1 = p[1];
                bR[0] = v0.x; bR[1] = v0.y; bR[2] = v0.z; bR[3] = v0.w;
                bR[4] = v1.x; bR[5] = v1.y; bR[6] = v1.z; bR[7] = v1.w;
            } else {
#pragma unroll
                for (int i = 0; i < 8; i++) bR[i] = 0.0f;
            }
#pragma unroll
            for (int i = 0; i < 8; i++) bR[i] = wmma::__float_to_tf32(bR[i]);
        }

        const float* As = sh.m.A[cur];
        const float* Bs = sh.m.B[cur];
#pragma unroll
        for (int ks = 0; ks < 16; ks += 8) {
            wmma::fragment<wmma::matrix_a, 16, 16, 8, wmma::precision::tf32, wmma::row_major> af[2];
            wmma::fragment<wmma::matrix_b, 16, 16, 8, wmma::precision::tf32, wmma::row_major> bf[4];
#pragma unroll
            for (int i = 0; i < 2; i++)
                wmma::load_matrix_sync(af[i], As + (wr * 32 + i * 16) * 20 + ks, 20);
#pragma unroll
            for (int j = 0; j < 4; j++)
                wmma::load_matrix_sync(bf[j], Bs + ks * 132 + wc * 64 + j * 16, 132);
#pragma unroll
            for (int i = 0; i < 2; i++)
#pragma unroll
                for (int j = 0; j < 4; j++)
                    wmma::mma_sync(acc[i][j], af[i], bf[j], acc[i][j]);
        }

        if (more) {
            float* As2 = sh.m.A[cur ^ 1];
            float* Bs2 = sh.m.B[cur ^ 1];
#pragma unroll
            for (int i = 0; i < 8; i++) As2[arow * 20 + akb + i] = aR[i];
#pragma unroll
            for (int i = 0; i < 8; i++) Bs2[bkk * 132 + bnn + i] = bR[i];
        }
        __syncthreads();
        cur ^= 1;
    }

    // Epilogue: bias + permuted store via shared staging, two column halves.
#pragma unroll
    for (int h = 0; h < 2; ++h) {
        if (wc == h) {
#pragma unroll
            for (int i = 0; i < 2; i++)
#pragma unroll
                for (int j = 0; j < 4; j++)
                    wmma::store_matrix_sync(
                        sh.stage + (wr * 32 + i * 16) * 68 + j * 16,
                        acc[i][j], 68, wmma::mem_row_major);
        }
        __syncthreads();
        for (int e = tid; e < 128 * 64; e += 256) {
            int row = e >> 6, cc = e & 63;
            int l1 = n0 + h * 64 + cc;
            float v = sh.stage[row * 68 + cc] + b1[(j1 << 10) + l1];
            int r = l1 & 15, p2 = l1 >> 4;
            g_h1p[(((m0 + row) * 64 + j1) << 10) + r * 64 + p2] = v;
        }
        __syncthreads();
    }
}

// ---------------------------------------------------------------------------
// GEMM2: per j2, out[b,j2,0:16] = h1p-slice[b,0:16] @ k2[j2][16x16] + b2[j2]
// fully coalesced (16 contiguous floats in, 16 contiguous out). fp32 exact.
// ---------------------------------------------------------------------------
__global__ __launch_bounds__(128) void gemm2_kernel(
    const float* __restrict__ k2, const float* __restrict__ b2)
{
    const int j2  = blockIdx.x;
    const int bg  = blockIdx.y;
    const int tid = threadIdx.x;

    __shared__ float wgt[256];
    __shared__ float bias[16];

    reinterpret_cast<float2*>(wgt)[tid] =
        reinterpret_cast<const float2*>(k2 + j2 * 256)[tid];
    if (tid < 16) bias[tid] = b2[j2 * 16 + tid];
    __syncthreads();

    const int r    = j2 >> 8;
    const int j1   = (j2 >> 2) & 63;
    const int p2hi = j2 & 3;
    const int b    = bg * 128 + tid;

    const float4* src = reinterpret_cast<const float4*>(
        g_h1p + (((b * 64 + j1) << 10) + (r << 6) + (p2hi << 4)));
    float in[16];
#pragma unroll
    for (int q = 0; q < 4; q++) {
        float4 v = src[q];
        in[q * 4 + 0] = v.x; in[q * 4 + 1] = v.y;
        in[q * 4 + 2] = v.z; in[q * 4 + 3] = v.w;
    }

    float out[16];
#pragma unroll
    for (int l = 0; l < 16; l++) out[l] = bias[l];
#pragma unroll
    for (int k = 0; k < 16; k++) {
        float a = in[k];
#pragma unroll
        for (int l = 0; l < 16; l++) out[l] += a * wgt[k * 16 + l];
    }

    const int j3 = r * 4 + (j1 >> 4);
    float4* dst = reinterpret_cast<float4*>(
        g_h2r + (((b * 64 + j3) << 10) + ((j1 & 15) << 6) + (p2hi << 4)));
#pragma unroll
    for (int q = 0; q < 4; q++)
        dst[q] = make_float4(out[q * 4 + 0], out[q * 4 + 1],
                             out[q * 4 + 2], out[q * 4 + 3]);
}

// ---------------------------------------------------------------------------
// GEMM3: per j3, C[1024x200] = h2r[1024x1024] @ k3[j3][1024x200] + b3[j3]
// output scattered to final [B,80,80,2] layout.
// ---------------------------------------------------------------------------
__global__ __launch_bounds__(256) void gemm3_kernel(
    const float* __restrict__ k3w, const float* __restrict__ b3,
    float* __restrict__ out)
{
    const int n0  = blockIdx.x * 128;   // 0 or 128
    const int m0  = blockIdx.y * 128;
    const int j3  = blockIdx.z;
    const int tid = threadIdx.x;

    __shared__ SmemU sh;

    const int w  = tid >> 5;
    const int wr = w >> 1;
    const int wc = w & 1;

    wmma::fragment<wmma::accumulator, 16, 16, 8, float> acc[2][4];
#pragma unroll
    for (int i = 0; i < 2; i++)
#pragma unroll
        for (int j = 0; j < 4; j++) wmma::fill_fragment(acc[i][j], 0.0f);

    const int arow = tid >> 1;
    const int akb  = (tid & 1) * 8;
    const int bkk  = tid >> 4;
    const int bnn  = (tid & 15) * 8;
    const int bidx = m0 + arow;
    const int abase = ((bidx * 64 + j3) << 10);
    const int wbase = j3 * 204800;

    float aR[8], bR[8];

    // prefetch chunk 0
    {
        const float4* p = reinterpret_cast<const float4*>(g_h2r + abase + akb);
        float4 v0 = p[0], v1 = p[1];
        aR[0] = v0.x; aR[1] = v0.y; aR[2] = v0.z; aR[3] = v0.w;
        aR[4] = v1.x; aR[5] = v1.y; aR[6] = v1.z; aR[7] = v1.w;
#pragma unroll
        for (int i = 0; i < 8; i++) aR[i] = wmma::__float_to_tf32(aR[i]);

        const float* bp = k3w + wbase + bkk * 200 + n0 + bnn;
        if (n0 + bnn + 8 <= 200) {
            const float4* q = reinterpret_cast<const float4*>(bp);
            float4 u0 = q[0], u1 = q[1];
            bR[0] = u0.x; bR[1] = u0.y; bR[2] = u0.z; bR[3] = u0.w;
            bR[4] = u1.x; bR[5] = u1.y; bR[6] = u1.z; bR[7] = u1.w;
        } else {
#pragma unroll
            for (int i = 0; i < 8; i++)
                bR[i] = (n0 + bnn + i < 200) ? bp[i] : 0.0f;
        }
#pragma unroll
        for (int i = 0; i < 8; i++) bR[i] = wmma::__float_to_tf32(bR[i]);

        float* As = sh.m.A[0];
        float* Bs = sh.m.B[0];
#pragma unroll
        for (int i = 0; i < 8; i++) As[arow * 20 + akb + i] = aR[i];
#pragma unroll
        for (int i = 0; i < 8; i++) Bs[bkk * 132 + bnn + i] = bR[i];
    }
    __syncthreads();

    int cur = 0;
    const int NC = 64;  // K = 1024
    for (int cidx = 0; cidx < NC; ++cidx) {
        const bool more = (cidx + 1 < NC);
        if (more) {
            const int kt = (cidx + 1) * 16;
            const float4* p = reinterpret_cast<const float4*>(g_h2r + abase + kt + akb);
            float4 v0 = p[0], v1 = p[1];
            aR[0] = v0.x; aR[1] = v0.y; aR[2] = v0.z; aR[3] = v0.w;
            aR[4] = v1.x; aR[5] = v1.y; aR[6] = v1.z; aR[7] = v1.w;
#pragma unroll
            for (int i = 0; i < 8; i++) aR[i] = wmma::__float_to_tf32(aR[i]);

            const float* bp = k3w + wbase + (kt + bkk) * 200 + n0 + bnn;
            if (n0 + bnn + 8 <= 200) {
                const float4* q = reinterpret_cast<const float4*>(bp);
                float4 u0 = q[0], u1 = q[1];
                bR[0] = u0.x; bR[1] = u0.y; bR[2] = u0.z; bR[3] = u0.w;
                bR[4] = u1.x; bR[5] = u1.y; bR[6] = u1.z; bR[7] = u1.w;
            } else {
#pragma unroll
                for (int i = 0; i < 8; i++)
                    bR[i] = (n0 + bnn + i < 200) ? bp[i] : 0.0f;
            }
#pragma unroll
            for (int i = 0; i < 8; i++) bR[i] = wmma::__float_to_tf32(bR[i]);
        }

        const float* As = sh.m.A[cur];
        const float* Bs = sh.m.B[cur];
#pragma unroll
        for (int ks = 0; ks < 16; ks += 8) {
            wmma::fragment<wmma::matrix_a, 16, 16, 8, wmma::precision::tf32, wmma::row_major> af[2];
            wmma::fragment<wmma::matrix_b, 16, 16, 8, wmma::precision::tf32, wmma::row_major> bf[4];
#pragma unroll
            for (int i = 0; i < 2; i++)
                wmma::load_matrix_sync(af[i], As + (wr * 32 + i * 16) * 20 + ks, 20);
#pragma unroll
            for (int j = 0; j < 4; j++)
                wmma::load_matrix_sync(bf[j], Bs + ks * 132 + wc * 64 + j * 16, 132);
#pragma unroll
            for (int i = 0; i < 2; i++)
#pragma unroll
                for (int j = 0; j < 4; j++)
                    wmma::mma_sync(acc[i][j], af[i], bf[j], acc[i][j]);
        }

        if (more) {
            float* As2 = sh.m.A[cur ^ 1];
            float* Bs2 = sh.m.B[cur ^ 1];
#pragma unroll
            for (int i = 0; i < 8; i++) As2[arow * 20 + akb + i] = aR[i];
#pragma unroll
            for (int i = 0; i < 8; i++) Bs2[bkk * 132 + bnn + i] = bR[i];
        }
        __syncthreads();
        cur ^= 1;
    }

    // Epilogue: bias + scatter to [B,80,80,2]
#pragma unroll
    for (int h = 0; h < 2; ++h) {
        if (wc == h) {
#pragma unroll
            for (int i = 0; i < 2; i++)
#pragma unroll
                for (int j = 0; j < 4; j++)
                    wmma::store_matrix_sync(
                        sh.stage + (wr * 32 + i * 16) * 68 + j * 16,
                        acc[i][j], 68, wmma::mem_row_major);
        }
        __syncthreads();
        for (int e = tid; e < 128 * 64; e += 256) {
            int row = e >> 6, cc = e & 63;
            int l3 = n0 + h * 64 + cc;
            if (l3 < 200) {
                float v = sh.stage[row * 68 + cc] + b3[j3 * 200 + l3];
                int wq  = l3 >> 1, c = l3 & 1;
                int w2x = wq / 10;
                int w2y = wq - w2x * 10;
                int b2x = j3 >> 3, b2y = j3 & 7;
                out[(m0 + row) * 12800 +
                    ((b2x * 10 + w2x) * 80 + b2y * 10 + w2y) * 2 + c] = v;
            }
        }
        __syncthreads();
    }
}

extern "C" void kernel_launch(void* const* d_in, const int* in_sizes, int n_in,
                              void* d_out, int out_size) {
    const float* x   = (const float*)d_in[0];
    const float* k1  = (const float*)d_in[1];
    const float* b1  = (const float*)d_in[2];
    const float* k2  = (const float*)d_in[3];
    const float* b2  = (const float*)d_in[4];
    const float* k3w = (const float*)d_in[5];
    const float* b3  = (const float*)d_in[6];
    float* out = (float*)d_out;

    gemm1_kernel<<<dim3(8, 8, 64), 256>>>(x, k1, b1);
    gemm2_kernel<<<dim3(4096, 8), 128>>>(k2, b2);
    gemm3_kernel<<<dim3(2, 8, 64), 256>>>(k3w, b3, out);
}

// round 4
// speedup vs baseline: 2.8257x; 2.8257x over previous
#include <cuda_runtime.h>
#include <cuda_fp16.h>
#include <mma.h>
#include <cstdint>

using namespace nvcuda;

// Scratch (__device__ globals; runtime alloc forbidden)
__device__ __half g_xa [14680064];  // [64 j1][1024 b][224 kpad]   fp16
__device__ __half g_k1t[14680064];  // [64 j1][1024 l1][224 kpad]  fp16
__device__ __half g_k3t[16777216];  // [64 j3][256 l3pad][1024 k3] fp16
__device__ __half g_h1p[67108864];  // [64 j1][16 r][64 p2][1024 b] fp16
__device__ __half g_h2r[67108864];  // [64 j3][1024 b][1024 k3]     fp16

__device__ __forceinline__ uint32_t smem_u32(const void* p) {
    uint32_t a;
    asm("{ .reg .u64 t; cvta.to.shared.u64 t, %1; cvt.u32.u64 %0, t; }"
        : "=r"(a) : "l"(p));
    return a;
}
__device__ __forceinline__ void cpa(uint32_t d, const void* s) {
    asm volatile("cp.async.cg.shared.global [%0], [%1], 16;" :: "r"(d), "l"(s));
}
__device__ __forceinline__ void cpcommit() { asm volatile("cp.async.commit_group;" ::: "memory"); }
__device__ __forceinline__ void cpwait0()  { asm volatile("cp.async.wait_group 0;" ::: "memory"); }
__device__ __forceinline__ void cpwait1()  { asm volatile("cp.async.wait_group 1;" ::: "memory"); }

// ------------------------- pre-kernels ------------------------------------
__global__ __launch_bounds__(256) void gather_x(const float* __restrict__ x) {
    const int b = blockIdx.x;
    const int j1 = blockIdx.y * 8 + (threadIdx.x >> 5);
    const int lane = threadIdx.x & 31;
    const int bx = j1 >> 3, by = j1 & 7;
    const float* xr = x + b * 12800;
    __half* dst = g_xa + (j1 * 1024 + b) * 224;
    for (int k = lane; k < 224; k += 32) {
        float v = 0.0f;
        if (k < 200) {
            int q = k >> 1, c = k & 1;
            int wx = q / 10, wy = q - wx * 10;
            v = xr[((bx * 10 + wx) * 80 + by * 10 + wy) * 2 + c];
        }
        dst[k] = __float2half_rn(v);
    }
}
__global__ void transpose_k1(const float* __restrict__ k1) {
    __shared__ float t[32][33];
    const int j1 = blockIdx.z, l0 = blockIdx.x * 32, k0 = blockIdx.y * 32;
    const int tx = threadIdx.x, ty = threadIdx.y;
#pragma unroll
    for (int r = 0; r < 32; r += 8) {
        int k = k0 + ty + r;
        t[ty + r][tx] = (k < 200) ? k1[(j1 * 200 + k) * 1024 + l0 + tx] : 0.0f;
    }
    __syncthreads();
#pragma unroll
    for (int r = 0; r < 32; r += 8)
        g_k1t[(j1 * 1024 + l0 + ty + r) * 224 + k0 + tx] = __float2half_rn(t[tx][ty + r]);
}
__global__ void transpose_k3(const float* __restrict__ k3) {
    __shared__ float t[32][33];
    const int j3 = blockIdx.z, k0 = blockIdx.x * 32, l0 = blockIdx.y * 32;
    const int tx = threadIdx.x, ty = threadIdx.y;
#pragma unroll
    for (int r = 0; r < 32; r += 8) {
        int l = l0 + tx, k = k0 + ty + r;
        t[ty + r][tx] = (l < 200) ? k3[(j3 * 1024 + k) * 200 + l] : 0.0f;
    }
    __syncthreads();
#pragma unroll
    for (int r = 0; r < 32; r += 8)
        g_k3t[(j3 * 256 + l0 + ty + r) * 1024 + k0 + tx] = __float2half_rn(t[tx][ty + r]);
}

// ------------------------- GEMM core (fp16 wmma) ---------------------------
// block tile 128(m) x 128(n), k-chunk 32, 8 warps each 32x64.
// smem: A[2] @ 0/12288 (128 rows x 48 halves), B[2] @ 24576/36864. 49152B.
// stage (fp32 128x68) aliases the same smem in the epilogue.

template <int NC>
__device__ __forceinline__ void gemm_mainloop(
    const __half* aS, int aStride, const __half* bS, int bStride,
    char* dsm, uint32_t sbase, int tid, int wr, int wc,
    wmma::fragment<wmma::accumulator, 16, 16, 16, float> (&acc)[2][4])
{
#pragma unroll
    for (int i = 0; i < 2; i++)
#pragma unroll
        for (int j = 0; j < 4; j++) wmma::fill_fragment(acc[i][j], 0.0f);

    // preload chunk 0 into buf 0
    {
        for (int i = tid; i < 512; i += 256) {
            int row = i >> 2, seg = i & 3;
            cpa(sbase + row * 96 + seg * 16, aS + row * aStride + seg * 8);
            cpa(sbase + 24576 + row * 96 + seg * 16, bS + row * bStride + seg * 8);
        }
        cpcommit();
    }
    for (int c = 0; c < NC; c++) {
        const int buf = c & 1;
        if (c + 1 < NC) {
            const int nb = (c + 1) & 1, k0 = (c + 1) * 32;
            for (int i = tid; i < 512; i += 256) {
                int row = i >> 2, seg = i & 3;
                cpa(sbase + nb * 12288 + row * 96 + seg * 16,
                    aS + row * aStride + k0 + seg * 8);
                cpa(sbase + 24576 + nb * 12288 + row * 96 + seg * 16,
                    bS + row * bStride + k0 + seg * 8);
            }
            cpcommit();
            cpwait1();
        } else {
            cpwait0();
        }
        __syncthreads();

        const __half* As = (const __half*)(dsm + buf * 12288);
        const __half* Bs = (const __half*)(dsm + 24576 + buf * 12288);
#pragma unroll
        for (int kk = 0; kk < 32; kk += 16) {
            wmma::fragment<wmma::matrix_a, 16, 16, 16, __half, wmma::row_major> af[2];
            wmma::fragment<wmma::matrix_b, 16, 16, 16, __half, wmma::col_major> bf[4];
#pragma unroll
            for (int i = 0; i < 2; i++)
                wmma::load_matrix_sync(af[i], As + (wr * 32 + i * 16) * 48 + kk, 48);
#pragma unroll
            for (int j = 0; j < 4; j++)
                wmma::load_matrix_sync(bf[j], Bs + (wc * 64 + j * 16) * 48 + kk, 48);
#pragma unroll
            for (int i = 0; i < 2; i++)
#pragma unroll
                for (int j = 0; j < 4; j++)
                    wmma::mma_sync(acc[i][j], af[i], bf[j], acc[i][j]);
        }
        __syncthreads();
    }
}

// ------------------------- GEMM1 ------------------------------------------
__global__ __launch_bounds__(256) void g1(const float* __restrict__ b1) {
    extern __shared__ __align__(16) char dsm[];
    const int tid = threadIdx.x, wid = tid >> 5;
    const int wr = wid >> 1, wc = wid & 1;
    const int j1 = blockIdx.z, n0 = blockIdx.x * 128, m0 = blockIdx.y * 128;
    const uint32_t sbase = smem_u32(dsm);

    const __half* aS = g_xa  + (j1 * 1024 + m0) * 224;
    const __half* bS = g_k1t + (j1 * 1024 + n0) * 224;

    wmma::fragment<wmma::accumulator, 16, 16, 16, float> acc[2][4];
    gemm_mainloop<7>(aS, 224, bS, 224, dsm, sbase, tid, wr, wc, acc);

    float* stage = (float*)dsm;
#pragma unroll
    for (int h = 0; h < 2; ++h) {
        if (wc == h) {
#pragma unroll
            for (int i = 0; i < 2; i++)
#pragma unroll
                for (int j = 0; j < 4; j++)
                    wmma::store_matrix_sync(
                        stage + (wr * 32 + i * 16) * 68 + j * 16,
                        acc[i][j], 68, wmma::mem_row_major);
        }
        __syncthreads();
        for (int e = tid; e < 8192; e += 256) {
            int cc = e >> 7, row = e & 127;
            int l1 = n0 + h * 64 + cc;
            float v = stage[row * 68 + cc] + b1[(j1 << 10) + l1];
            g_h1p[((j1 * 16 + (l1 & 15)) * 64 + (l1 >> 4)) * 1024 + m0 + row] =
                __float2half_rn(v);
        }
        __syncthreads();
    }
}

// ------------------------- GEMM2 (fp32 math, fp16 I/O) ---------------------
__global__ __launch_bounds__(128) void g2(const float* __restrict__ k2,
                                          const float* __restrict__ b2) {
    const int j2 = blockIdx.x, tid = threadIdx.x;
    __shared__ float wgt[256];
    __shared__ float bias[16];
    reinterpret_cast<float2*>(wgt)[tid] =
        reinterpret_cast<const float2*>(k2 + j2 * 256)[tid];
    if (tid < 16) bias[tid] = b2[j2 * 16 + tid];
    __syncthreads();

    const int r = j2 >> 8, j1 = (j2 >> 2) & 63, p2hi = j2 & 3;
    const int b = blockIdx.y * 128 + tid;
    const __half* src = g_h1p + ((j1 * 16 + r) * 64 + p2hi * 16) * 1024 + b;
    float in[16];
#pragma unroll
    for (int k = 0; k < 16; k++) in[k] = __half2float(src[k * 1024]);
    float out[16];
#pragma unroll
    for (int l = 0; l < 16; l++) out[l] = bias[l];
#pragma unroll
    for (int k = 0; k < 16; k++) {
        float a = in[k];
#pragma unroll
        for (int l = 0; l < 16; l++) out[l] += a * wgt[k * 16 + l];
    }
    __half2 ph[8];
#pragma unroll
    for (int q = 0; q < 8; q++)
        ph[q] = __floats2half2_rn(out[2 * q], out[2 * q + 1]);
    __half* dp = g_h2r + ((size_t)(r * 4 + (j1 >> 4)) * 1024 + b) * 1024 +
                 (j1 & 15) * 64 + p2hi * 16;
    reinterpret_cast<uint4*>(dp)[0] = reinterpret_cast<uint4*>(ph)[0];
    reinterpret_cast<uint4*>(dp)[1] = reinterpret_cast<uint4*>(ph)[1];
}

// ------------------------- GEMM3 ------------------------------------------
__global__ __launch_bounds__(256) void g3(const float* __restrict__ b3,
                                          float* __restrict__ out) {
    extern __shared__ __align__(16) char dsm[];
    const int tid = threadIdx.x, wid = tid >> 5;
    const int wr = wid >> 1, wc = wid & 1;
    const int j3 = blockIdx.z, n0 = blockIdx.x * 128, m0 = blockIdx.y * 128;
    const uint32_t sbase = smem_u32(dsm);

    const __half* aS = g_h2r + ((size_t)(j3 * 1024 + m0)) * 1024;
    const __half* bS = g_k3t + ((size_t)(j3 * 256 + n0)) * 1024;

    wmma::fragment<wmma::accumulator, 16, 16, 16, float> acc[2][4];
    gemm_mainloop<32>(aS, 1024, bS, 1024, dsm, sbase, tid, wr, wc, acc);

    float* stage = (float*)dsm;
    const int b2x = j3 >> 3, b2y = j3 & 7;
#pragma unroll
    for (int h = 0; h < 2; ++h) {
        if (wc == h) {
#pragma unroll
            for (int i = 0; i < 2; i++)
#pragma unroll
                for (int j = 0; j < 4; j++)
                    wmma::store_matrix_sync(
                        stage + (wr * 32 + i * 16) * 68 + j * 16,
                        acc[i][j], 68, wmma::mem_row_major);
        }
        __syncthreads();
        for (int e = tid; e < 8192; e += 256) {
            int cc = e & 63, row = e >> 6;
            int l3 = n0 + h * 64 + cc;
            if (l3 < 200) {
                float v = stage[row * 68 + cc] + b3[j3 * 200 + l3];
                int q = l3 >> 1, c = l3 & 1;
                int w2x = q / 10, w2y = q - w2x * 10;
                out[(m0 + row) * 12800 +
                    ((b2x * 10 + w2x) * 80 + b2y * 10 + w2y) * 2 + c] = v;
            }
        }
        __syncthreads();
    }
}

extern "C" void kernel_launch(void* const* d_in, const int* in_sizes, int n_in,
                              void* d_out, int out_size) {
    const float* x   = (const float*)d_in[0];
    const float* k1  = (const float*)d_in[1];
    const float* b1  = (const float*)d_in[2];
    const float* k2  = (const float*)d_in[3];
    const float* b2  = (const float*)d_in[4];
    const float* k3w = (const float*)d_in[5];
    const float* b3  = (const float*)d_in[6];
    float* out = (float*)d_out;

    gather_x    <<<dim3(1024, 8), 256>>>(x);
    transpose_k1<<<dim3(32, 7, 64), dim3(32, 8)>>>(k1);
    transpose_k3<<<dim3(32, 8, 64), dim3(32, 8)>>>(k3w);
    g1<<<dim3(8, 8, 64), 256, 49152>>>(b1);
    g2<<<dim3(4096, 8), 128>>>(k2, b2);
    g3<<<dim3(2, 8, 64), 256, 49152>>>(b3, out);
}

// round 5
// speedup vs baseline: 3.1071x; 1.0996x over previous
#include <cuda_runtime.h>
#include <cuda_fp16.h>
#include <mma.h>
#include <cstdint>

using namespace nvcuda;

// Scratch (__device__ globals; runtime alloc forbidden)
__device__ __half g_xa [14680064];  // [64 j1][1024 b][224 kpad]   fp16
__device__ __half g_k1t[14680064];  // [64 j1][1024 l1][224 kpad]  fp16
__device__ __half g_k3t[16777216];  // [64 j3][256 l3pad][1024 k3] fp16
__device__ __half g_h1p[67108864];  // [64 j1][16 r][64 p2][1024 b] fp16
__device__ __half g_h2r[67108864];  // [64 j3][1024 b][1024 k3]     fp16

__device__ __forceinline__ uint32_t smem_u32(const void* p) {
    uint32_t a;
    asm("{ .reg .u64 t; cvta.to.shared.u64 t, %1; cvt.u32.u64 %0, t; }"
        : "=r"(a) : "l"(p));
    return a;
}
__device__ __forceinline__ void cpa(uint32_t d, const void* s) {
    asm volatile("cp.async.cg.shared.global [%0], [%1], 16;" :: "r"(d), "l"(s));
}
__device__ __forceinline__ void cpcommit() { asm volatile("cp.async.commit_group;" ::: "memory"); }
__device__ __forceinline__ void cpwait0()  { asm volatile("cp.async.wait_group 0;" ::: "memory"); }
__device__ __forceinline__ void cpwait1()  { asm volatile("cp.async.wait_group 1;" ::: "memory"); }

// smem layout (halves): row stride 56 (112B) -> LDSM banks (28*r)%32 all
// distinct per 8-row phase => conflict-free fragment loads.
// A buffers @ 0 / 14336, B buffers @ 28672 / 43008. Total 57344 B.
#define LDM       56
#define ROWB      112
#define ABUF(buf) ((buf) * 14336)
#define BBUF(buf) (28672 + (buf) * 14336)

// ------------------------- pre-kernels ------------------------------------
__global__ __launch_bounds__(256) void gather_x(const float* __restrict__ x) {
    const int b = blockIdx.x;
    const int j1 = blockIdx.y * 8 + (threadIdx.x >> 5);
    const int lane = threadIdx.x & 31;
    const int bx = j1 >> 3, by = j1 & 7;
    const float* xr = x + b * 12800;
    __half* dst = g_xa + (j1 * 1024 + b) * 224;
    for (int k = lane; k < 224; k += 32) {
        float v = 0.0f;
        if (k < 200) {
            int q = k >> 1, c = k & 1;
            int wx = q / 10, wy = q - wx * 10;
            v = xr[((bx * 10 + wx) * 80 + by * 10 + wy) * 2 + c];
        }
        dst[k] = __float2half_rn(v);
    }
}
__global__ void transpose_k1(const float* __restrict__ k1) {
    __shared__ float t[32][33];
    const int j1 = blockIdx.z, l0 = blockIdx.x * 32, k0 = blockIdx.y * 32;
    const int tx = threadIdx.x, ty = threadIdx.y;
#pragma unroll
    for (int r = 0; r < 32; r += 8) {
        int k = k0 + ty + r;
        t[ty + r][tx] = (k < 200) ? k1[(j1 * 200 + k) * 1024 + l0 + tx] : 0.0f;
    }
    __syncthreads();
#pragma unroll
    for (int r = 0; r < 32; r += 8)
        g_k1t[(j1 * 1024 + l0 + ty + r) * 224 + k0 + tx] = __float2half_rn(t[tx][ty + r]);
}
__global__ void transpose_k3(const float* __restrict__ k3) {
    __shared__ float t[32][33];
    const int j3 = blockIdx.z, k0 = blockIdx.x * 32, l0 = blockIdx.y * 32;
    const int tx = threadIdx.x, ty = threadIdx.y;
#pragma unroll
    for (int r = 0; r < 32; r += 8) {
        int l = l0 + tx, k = k0 + ty + r;
        t[ty + r][tx] = (l < 200) ? k3[(j3 * 1024 + k) * 200 + l] : 0.0f;
    }
    __syncthreads();
#pragma unroll
    for (int r = 0; r < 32; r += 8)
        g_k3t[(j3 * 256 + l0 + ty + r) * 1024 + k0 + tx] = __float2half_rn(t[tx][ty + r]);
}

// ------------------------- GEMM core (fp16 wmma) ---------------------------
// block tile 128(m) x 128(n), k-chunk 32, 8 warps each 32x64.
template <int NC>
__device__ __forceinline__ void gemm_mainloop(
    const __half* aS, int aStride, const __half* bS, int bStride,
    char* dsm, uint32_t sbase, int tid, int wr, int wc,
    wmma::fragment<wmma::accumulator, 16, 16, 16, float> (&acc)[2][4])
{
#pragma unroll
    for (int i = 0; i < 2; i++)
#pragma unroll
        for (int j = 0; j < 4; j++) wmma::fill_fragment(acc[i][j], 0.0f);

    // preload chunk 0 into buf 0
    {
        for (int i = tid; i < 512; i += 256) {
            int row = i >> 2, seg = i & 3;
            cpa(sbase + ABUF(0) + row * ROWB + seg * 16, aS + row * aStride + seg * 8);
            cpa(sbase + BBUF(0) + row * ROWB + seg * 16, bS + row * bStride + seg * 8);
        }
        cpcommit();
    }
    for (int c = 0; c < NC; c++) {
        const int buf = c & 1;
        if (c + 1 < NC) {
            const int nb = (c + 1) & 1, k0 = (c + 1) * 32;
            for (int i = tid; i < 512; i += 256) {
                int row = i >> 2, seg = i & 3;
                cpa(sbase + ABUF(nb) + row * ROWB + seg * 16,
                    aS + row * aStride + k0 + seg * 8);
                cpa(sbase + BBUF(nb) + row * ROWB + seg * 16,
                    bS + row * bStride + k0 + seg * 8);
            }
            cpcommit();
            cpwait1();
        } else {
            cpwait0();
        }
        __syncthreads();

        const __half* As = (const __half*)(dsm + ABUF(buf));
        const __half* Bs = (const __half*)(dsm + BBUF(buf));
#pragma unroll
        for (int kk = 0; kk < 32; kk += 16) {
            wmma::fragment<wmma::matrix_a, 16, 16, 16, __half, wmma::row_major> af[2];
            wmma::fragment<wmma::matrix_b, 16, 16, 16, __half, wmma::col_major> bf[4];
#pragma unroll
            for (int i = 0; i < 2; i++)
                wmma::load_matrix_sync(af[i], As + (wr * 32 + i * 16) * LDM + kk, LDM);
#pragma unroll
            for (int j = 0; j < 4; j++)
                wmma::load_matrix_sync(bf[j], Bs + (wc * 64 + j * 16) * LDM + kk, LDM);
#pragma unroll
            for (int i = 0; i < 2; i++)
#pragma unroll
                for (int j = 0; j < 4; j++)
                    wmma::mma_sync(acc[i][j], af[i], bf[j], acc[i][j]);
        }
        __syncthreads();
    }
}

// ------------------------- GEMM1 ------------------------------------------
__global__ __launch_bounds__(256, 2) void g1(const float* __restrict__ b1) {
    extern __shared__ __align__(16) char dsm[];
    const int tid = threadIdx.x, wid = tid >> 5;
    const int wr = wid >> 1, wc = wid & 1;
    const int j1 = blockIdx.z, n0 = blockIdx.x * 128, m0 = blockIdx.y * 128;
    const uint32_t sbase = smem_u32(dsm);

    const __half* aS = g_xa  + (j1 * 1024 + m0) * 224;
    const __half* bS = g_k1t + (j1 * 1024 + n0) * 224;

    wmma::fragment<wmma::accumulator, 16, 16, 16, float> acc[2][4];
    gemm_mainloop<7>(aS, 224, bS, 224, dsm, sbase, tid, wr, wc, acc);

    float* stage = (float*)dsm;
#pragma unroll
    for (int h = 0; h < 2; ++h) {
        if (wc == h) {
#pragma unroll
            for (int i = 0; i < 2; i++)
#pragma unroll
                for (int j = 0; j < 4; j++)
                    wmma::store_matrix_sync(
                        stage + (wr * 32 + i * 16) * 68 + j * 16,
                        acc[i][j], 68, wmma::mem_row_major);
        }
        __syncthreads();
        for (int e = tid; e < 8192; e += 256) {
            int cc = e >> 7, row = e & 127;
            int l1 = n0 + h * 64 + cc;
            float v = stage[row * 68 + cc] + b1[(j1 << 10) + l1];
            g_h1p[((j1 * 16 + (l1 & 15)) * 64 + (l1 >> 4)) * 1024 + m0 + row] =
                __float2half_rn(v);
        }
        __syncthreads();
    }
}

// ------------------------- GEMM2 (fp32 math, fp16 I/O) ---------------------
__global__ __launch_bounds__(128) void g2(const float* __restrict__ k2,
                                          const float* __restrict__ b2) {
    const int j2 = blockIdx.x, tid = threadIdx.x;
    __shared__ float wgt[256];
    __shared__ float bias[16];
    reinterpret_cast<float2*>(wgt)[tid] =
        reinterpret_cast<const float2*>(k2 + j2 * 256)[tid];
    if (tid < 16) bias[tid] = b2[j2 * 16 + tid];
    __syncthreads();

    const int r = j2 >> 8, j1 = (j2 >> 2) & 63, p2hi = j2 & 3;
    const int b = blockIdx.y * 128 + tid;
    const __half* src = g_h1p + ((j1 * 16 + r) * 64 + p2hi * 16) * 1024 + b;
    float in[16];
#pragma unroll
    for (int k = 0; k < 16; k++) in[k] = __half2float(src[k * 1024]);
    float out[16];
#pragma unroll
    for (int l = 0; l < 16; l++) out[l] = bias[l];
#pragma unroll
    for (int k = 0; k < 16; k++) {
        float a = in[k];
#pragma unroll
        for (int l = 0; l < 16; l++) out[l] += a * wgt[k * 16 + l];
    }
    __half2 ph[8];
#pragma unroll
    for (int q = 0; q < 8; q++)
        ph[q] = __floats2half2_rn(out[2 * q], out[2 * q + 1]);
    __half* dp = g_h2r + ((size_t)(r * 4 + (j1 >> 4)) * 1024 + b) * 1024 +
                 (j1 & 15) * 64 + p2hi * 16;
    reinterpret_cast<uint4*>(dp)[0] = reinterpret_cast<uint4*>(ph)[0];
    reinterpret_cast<uint4*>(dp)[1] = reinterpret_cast<uint4*>(ph)[1];
}

// ------------------------- GEMM3 ------------------------------------------
__global__ __launch_bounds__(256, 2) void g3(const float* __restrict__ b3,
                                             float* __restrict__ out) {
    extern __shared__ __align__(16) char dsm[];
    const int tid = threadIdx.x, wid = tid >> 5;
    const int wr = wid >> 1, wc = wid & 1;
    const int j3 = blockIdx.z, n0 = blockIdx.x * 128, m0 = blockIdx.y * 128;
    const uint32_t sbase = smem_u32(dsm);

    const __half* aS = g_h2r + ((size_t)(j3 * 1024 + m0)) * 1024;
    const __half* bS = g_k3t + ((size_t)(j3 * 256 + n0)) * 1024;

    wmma::fragment<wmma::accumulator, 16, 16, 16, float> acc[2][4];
    gemm_mainloop<32>(aS, 1024, bS, 1024, dsm, sbase, tid, wr, wc, acc);

    float* stage = (float*)dsm;
    const int b2x = j3 >> 3, b2y = j3 & 7;
#pragma unroll
    for (int h = 0; h < 2; ++h) {
        if (wc == h) {
#pragma unroll
            for (int i = 0; i < 2; i++)
#pragma unroll
                for (int j = 0; j < 4; j++)
                    wmma::store_matrix_sync(
                        stage + (wr * 32 + i * 16) * 68 + j * 16,
                        acc[i][j], 68, wmma::mem_row_major);
        }
        __syncthreads();
        for (int e = tid; e < 8192; e += 256) {
            int cc = e & 63, row = e >> 6;
            int l3 = n0 + h * 64 + cc;
            if (l3 < 200) {
                float v = stage[row * 68 + cc] + b3[j3 * 200 + l3];
                int q = l3 >> 1, c = l3 & 1;
                int w2x = q / 10, w2y = q - w2x * 10;
                out[(m0 + row) * 12800 +
                    ((b2x * 10 + w2x) * 80 + b2y * 10 + w2y) * 2 + c] = v;
            }
        }
        __syncthreads();
    }
}

extern "C" void kernel_launch(void* const* d_in, const int* in_sizes, int n_in,
                              void* d_out, int out_size) {
    const float* x   = (const float*)d_in[0];
    const float* k1  = (const float*)d_in[1];
    const float* b1  = (const float*)d_in[2];
    const float* k2  = (const float*)d_in[3];
    const float* b2  = (const float*)d_in[4];
    const float* k3w = (const float*)d_in[5];
    const float* b3  = (const float*)d_in[6];
    float* out = (float*)d_out;

    const int SMEM = 57344;
    cudaFuncSetAttribute(g1, cudaFuncAttributeMaxDynamicSharedMemorySize, SMEM);
    cudaFuncSetAttribute(g3, cudaFuncAttributeMaxDynamicSharedMemorySize, SMEM);

    gather_x    <<<dim3(1024, 8), 256>>>(x);
    transpose_k1<<<dim3(32, 7, 64), dim3(32, 8)>>>(k1);
    transpose_k3<<<dim3(32, 8, 64), dim3(32, 8)>>>(k3w);
    g1<<<dim3(8, 8, 64), 256, SMEM>>>(b1);
    g2<<<dim3(4096, 8), 128>>>(k2, b2);
    g3<<<dim3(2, 8, 64), 256, SMEM>>>(b3, out);
}